// round 5
// baseline (speedup 1.0000x reference)
#include <cuda_runtime.h>

#define NN 50000
#define EE 800000

// ---------------- scratch (device globals; referenced directly in device code) ----------------
__device__ float g_buf0[NN * 96];   // GEMM output (xs = dinv * XW)
__device__ float g_buf1[NN * 96];   // aggregation output / next layer input
__device__ int   g_deg[NN];
__device__ float g_dinv[NN];
__device__ int   g_off[NN + 1];
__device__ int   g_cur[NN];
__device__ int   g_esrc[EE];
__device__ int   g_bsum[128];

// ---------------- CSR build ----------------
__global__ void k_zero_deg() {
    int i = blockIdx.x * blockDim.x + threadIdx.x;
    if (i < NN) g_deg[i] = 0;
}

__global__ void k_count(const int* __restrict__ dst) {
    int e = blockIdx.x * blockDim.x + threadIdx.x;
    if (e < EE) atomicAdd(&g_deg[dst[e]], 1);
}

__global__ void k_scan1() {
    __shared__ int sh[512];
    int t = threadIdx.x;
    int i = blockIdx.x * 512 + t;
    int v = (i < NN) ? g_deg[i] : 0;
    sh[t] = v;
    for (int o = 1; o < 512; o <<= 1) {
        __syncthreads();
        int tmp = (t >= o) ? sh[t - o] : 0;
        __syncthreads();
        sh[t] += tmp;
    }
    __syncthreads();
    if (i < NN) g_off[i] = sh[t] - v;       // exclusive within block
    if (t == 511) g_bsum[blockIdx.x] = sh[511];
}

// parallel exclusive scan of <=128 block sums (Hillis-Steele in smem)
__global__ void k_scan2(int nb) {
    __shared__ int sh[128];
    int t = threadIdx.x;
    int v = (t < nb) ? g_bsum[t] : 0;
    sh[t] = v;
#pragma unroll
    for (int o = 1; o < 128; o <<= 1) {
        __syncthreads();
        int tmp = (t >= o) ? sh[t - o] : 0;
        __syncthreads();
        sh[t] += tmp;
    }
    __syncthreads();
    if (t < nb) g_bsum[t] = sh[t] - v;      // exclusive
}

__global__ void k_scan3() {
    int i = blockIdx.x * blockDim.x + threadIdx.x;
    if (i < NN) {
        int o = g_off[i] + g_bsum[i >> 9];
        g_off[i] = o;
        g_cur[i] = o;
        g_dinv[i] = rsqrtf((float)(g_deg[i] + 1));   // +1 self-loop
    }
    if (i == 0) g_off[NN] = EE;
}

__global__ void k_fill(const int* __restrict__ src, const int* __restrict__ dst) {
    int e = blockIdx.x * blockDim.x + threadIdx.x;
    if (e < EE) {
        int d = dst[e];
        int p = atomicAdd(&g_cur[d], 1);
        g_esrc[p] = src[e];
    }
}

// ---------------- GEMM: g_buf0[row,:] = dinv[row] * (relu?(X[row,:]) @ W) ----------------
// Packed f32x2 version: row-pairs in 64-bit accumulators, fma.rn.f32x2 inner loop.
// 32 rows per block (8 warps x 4 rows), K-chunked into 32.
// Xs stored transposed ([kk][row], pad 34) so a row-pair is one LDS64 broadcast.
// W stored duplicated ((w,w) float2) so the multiplier pair is one LDS64.
template <int FOUT>
__global__ void k_gemm(const float* __restrict__ Xext, const float* __restrict__ W,
                       int in_sel, int K, int relu_in) {
    const float* X = (in_sel == 0) ? Xext : (const float*)g_buf1;
    __shared__ float2 Wd[32 * FOUT];     // duplicated pairs
    __shared__ float  Xs[32 * 34];       // [kk][row], padded stride 34
    const int t = threadIdx.x, lane = t & 31, warp = t >> 5;
    const int row0 = blockIdx.x * 32;
    constexpr int CJ = FOUT / 32;
    unsigned long long acc[2][CJ];       // [row-pair][col-group], packed f32x2
#pragma unroll
    for (int p = 0; p < 2; p++)
#pragma unroll
        for (int j = 0; j < CJ; j++) acc[p][j] = 0ULL;

    for (int k0 = 0; k0 < K; k0 += 32) {
        __syncthreads();
        // W tile, duplicated into both f32x2 lanes
        for (int i = t; i < 32 * FOUT; i += 256) {
            int kk = i / FOUT, c = i - kk * FOUT;
            float w = W[(k0 + kk) * FOUT + c];
            Wd[kk * FOUT + c] = make_float2(w, w);
        }
        // X tile, coalesced global read, transposed smem store
        for (int i = t; i < 32 * 32; i += 256) {
            int r = i >> 5, kk = i & 31;
            int row = row0 + r;
            float v = 0.f;
            if (row < NN) {
                v = X[row * K + k0 + kk];
                if (relu_in) v = fmaxf(v, 0.f);
            }
            Xs[kk * 34 + r] = v;
        }
        __syncthreads();
        const int rb = warp * 4;
#pragma unroll 4
        for (int kk = 0; kk < 32; kk++) {
            unsigned long long a01 = *(const unsigned long long*)&Xs[kk * 34 + rb];
            unsigned long long a23 = *(const unsigned long long*)&Xs[kk * 34 + rb + 2];
#pragma unroll
            for (int j = 0; j < CJ; j++) {
                unsigned long long w2 = *(const unsigned long long*)&Wd[kk * FOUT + lane + 32 * j];
                asm("fma.rn.f32x2 %0, %1, %2, %0;" : "+l"(acc[0][j]) : "l"(a01), "l"(w2));
                asm("fma.rn.f32x2 %0, %1, %2, %0;" : "+l"(acc[1][j]) : "l"(a23), "l"(w2));
            }
        }
    }
#pragma unroll
    for (int p = 0; p < 2; p++) {
        int rowA = row0 + warp * 4 + 2 * p;
        int rowB = rowA + 1;
        if (rowA < NN) {
            float sA = g_dinv[rowA];
            float sB = (rowB < NN) ? g_dinv[rowB] : 0.f;
#pragma unroll
            for (int j = 0; j < CJ; j++) {
                float lo, hi;
                asm("mov.b64 {%0, %1}, %2;" : "=f"(lo), "=f"(hi) : "l"(acc[p][j]));
                g_buf0[rowA * FOUT + lane + 32 * j] = sA * lo;
                if (rowB < NN) g_buf0[rowB * FOUT + lane + 32 * j] = sB * hi;
            }
        }
    }
}

// ---------------- aggregation: out[d] = dinv[d]*(xs[d] + sum_{src} xs[src]) + b ----------------
// 96-wide: warp per node, 24 lanes x float4. Reads g_buf0, writes g_buf1.
__global__ void k_agg96(const float* __restrict__ bias) {
    int wid = (blockIdx.x * blockDim.x + threadIdx.x) >> 5;
    int lane = threadIdx.x & 31;
    if (wid >= NN) return;
    int d = wid;
    int beg = g_off[d], end = g_off[d + 1];
    const float4* x4 = (const float4*)g_buf0;
    float4 acc = make_float4(0.f, 0.f, 0.f, 0.f);
    if (lane < 24) acc = x4[d * 24 + lane];   // self-loop
    for (int e = beg; e < end; e++) {
        int s = g_esrc[e];
        if (lane < 24) {
            float4 v = __ldg(&x4[s * 24 + lane]);
            acc.x += v.x; acc.y += v.y; acc.z += v.z; acc.w += v.w;
        }
    }
    if (lane < 24) {
        float sc = g_dinv[d];
        float4 b = ((const float4*)bias)[lane];
        float4 o;
        o.x = sc * acc.x + b.x; o.y = sc * acc.y + b.y;
        o.z = sc * acc.z + b.z; o.w = sc * acc.w + b.w;
        ((float4*)g_buf1)[d * 24 + lane] = o;
    }
}

// 32-wide: warp per node, 4 edge-groups of 8 lanes (float4), shfl reduce across groups.
// Reads g_buf0, writes external out.
__global__ void k_agg32(const float* __restrict__ bias, float* __restrict__ out) {
    int wid = (blockIdx.x * blockDim.x + threadIdx.x) >> 5;
    int lane = threadIdx.x & 31;
    if (wid >= NN) return;
    int d = wid;
    int grp = lane >> 3, fl = lane & 7;
    const float4* x4 = (const float4*)g_buf0;
    float4 acc = make_float4(0.f, 0.f, 0.f, 0.f);
    if (grp == 0) acc = x4[d * 8 + fl];       // self-loop
    int beg = g_off[d], end = g_off[d + 1];
    for (int e = beg + grp; e < end; e += 4) {
        int s = g_esrc[e];
        float4 v = __ldg(&x4[s * 8 + fl]);
        acc.x += v.x; acc.y += v.y; acc.z += v.z; acc.w += v.w;
    }
#pragma unroll
    for (int o = 8; o <= 16; o <<= 1) {
        acc.x += __shfl_xor_sync(0xFFFFFFFF, acc.x, o);
        acc.y += __shfl_xor_sync(0xFFFFFFFF, acc.y, o);
        acc.z += __shfl_xor_sync(0xFFFFFFFF, acc.z, o);
        acc.w += __shfl_xor_sync(0xFFFFFFFF, acc.w, o);
    }
    if (lane < 8) {
        float sc = g_dinv[d];
        float4 b = ((const float4*)bias)[fl];
        float4 o;
        o.x = sc * acc.x + b.x; o.y = sc * acc.y + b.y;
        o.z = sc * acc.z + b.z; o.w = sc * acc.w + b.w;
        ((float4*)out)[d * 8 + fl] = o;
    }
}

// ---------------- log_softmax over 32 classes: warp per node ----------------
__global__ void k_lsm(float* __restrict__ out) {
    int wid = (blockIdx.x * blockDim.x + threadIdx.x) >> 5;
    int lane = threadIdx.x & 31;
    if (wid >= NN) return;
    float v = out[wid * 32 + lane];
    float m = v;
#pragma unroll
    for (int o = 16; o >= 1; o >>= 1) m = fmaxf(m, __shfl_xor_sync(0xFFFFFFFF, m, o));
    float e = expf(v - m);
    float s = e;
#pragma unroll
    for (int o = 16; o >= 1; o >>= 1) s += __shfl_xor_sync(0xFFFFFFFF, s, o);
    out[wid * 32 + lane] = v - m - logf(s);
}

// ---------------- launch ----------------
extern "C" void kernel_launch(void* const* d_in, const int* in_sizes, int n_in,
                              void* d_out, int out_size) {
    const float* x  = (const float*)d_in[0];
    const int*   ei = (const int*)d_in[1];     // JAX x64 disabled -> int32
    const float* W1 = (const float*)d_in[2];
    const float* b1 = (const float*)d_in[3];
    const float* W2 = (const float*)d_in[4];
    const float* b2 = (const float*)d_in[5];
    const float* W3 = (const float*)d_in[6];
    const float* b3 = (const float*)d_in[7];
    float* out = (float*)d_out;

    const int* src = ei;
    const int* dst = ei + EE;

    const int NB_SCAN = (NN + 511) / 512;

    k_zero_deg<<<(NN + 255) / 256, 256>>>();
    k_count<<<(EE + 255) / 256, 256>>>(dst);
    k_scan1<<<NB_SCAN, 512>>>();
    k_scan2<<<1, 128>>>(NB_SCAN);
    k_scan3<<<(NN + 255) / 256, 256>>>();
    k_fill<<<(EE + 255) / 256, 256>>>(src, dst);

    const int GB = (NN + 31) / 32;           // gemm blocks
    const int AB = (NN * 32 + 255) / 256;    // warp-per-node blocks

    // layer 1: x[50000,128] @ W1[128,96]
    k_gemm<96><<<GB, 256>>>(x, W1, 0, 128, 0);
    k_agg96<<<AB, 256>>>(b1);
    // layer 2: relu(h1) @ W2[96,96]
    k_gemm<96><<<GB, 256>>>(x, W2, 1, 96, 1);
    k_agg96<<<AB, 256>>>(b2);
    // layer 3: relu(h2) @ W3[96,32]
    k_gemm<32><<<GB, 256>>>(x, W3, 1, 96, 1);
    k_agg32<<<AB, 256>>>(b3, out);

    k_lsm<<<AB, 256>>>(out);
}

// round 7
// speedup vs baseline: 1.4510x; 1.4510x over previous
#include <cuda_runtime.h>
#include <cuda_bf16.h>
#include <cstdint>

#define NN 50000
#define EE 800000

// ---------------- scratch (device globals) ----------------
__device__ float g_buf0[NN * 96];   // GEMM output (xs = dinv * XW)
__device__ float g_buf1[NN * 96];   // aggregation output / next layer input
__device__ int   g_deg[NN];
__device__ float g_dinv[NN];
__device__ int   g_off[NN + 1];
__device__ int   g_cur[NN];
__device__ int   g_esrc[EE];
__device__ int   g_bsum[128];

// ---------------- CSR build ----------------
__global__ void k_zero_deg() {
    int i = blockIdx.x * blockDim.x + threadIdx.x;
    if (i < NN) g_deg[i] = 0;
}

__global__ void k_count(const int* __restrict__ dst) {
    int e = blockIdx.x * blockDim.x + threadIdx.x;
    if (e < EE) atomicAdd(&g_deg[dst[e]], 1);
}

__global__ void k_scan1() {
    __shared__ int sh[512];
    int t = threadIdx.x;
    int i = blockIdx.x * 512 + t;
    int v = (i < NN) ? g_deg[i] : 0;
    sh[t] = v;
    for (int o = 1; o < 512; o <<= 1) {
        __syncthreads();
        int tmp = (t >= o) ? sh[t - o] : 0;
        __syncthreads();
        sh[t] += tmp;
    }
    __syncthreads();
    if (i < NN) g_off[i] = sh[t] - v;       // exclusive within block
    if (t == 511) g_bsum[blockIdx.x] = sh[511];
}

__global__ void k_scan2(int nb) {
    __shared__ int sh[128];
    int t = threadIdx.x;
    int v = (t < nb) ? g_bsum[t] : 0;
    sh[t] = v;
#pragma unroll
    for (int o = 1; o < 128; o <<= 1) {
        __syncthreads();
        int tmp = (t >= o) ? sh[t - o] : 0;
        __syncthreads();
        sh[t] += tmp;
    }
    __syncthreads();
    if (t < nb) g_bsum[t] = sh[t] - v;      // exclusive
}

__global__ void k_scan3() {
    int i = blockIdx.x * blockDim.x + threadIdx.x;
    if (i < NN) {
        int o = g_off[i] + g_bsum[i >> 9];
        g_off[i] = o;
        g_cur[i] = o;
        g_dinv[i] = rsqrtf((float)(g_deg[i] + 1));   // +1 self-loop
    }
    if (i == 0) g_off[NN] = EE;
}

__global__ void k_fill(const int* __restrict__ src, const int* __restrict__ dst) {
    int e = blockIdx.x * blockDim.x + threadIdx.x;
    if (e < EE) {
        int d = dst[e];
        int p = atomicAdd(&g_cur[d], 1);
        g_esrc[p] = src[e];
    }
}

// ---------------- GEMM (mma.sync m16n8k16, bf16 3-term split) ----------------
// g_buf0[row,:] = dinv[row] * (relu?(X[row,:]) @ W)
// 8 warps x m16 = 128 rows/block; K-chunks of 32; A [row][k], Bt [n][k],
// both padded to stride 40 (bank-conflict-free fragment loads).
#define MMA_BF16(C, A, B)                                                        \
    asm volatile(                                                                \
        "mma.sync.aligned.m16n8k16.row.col.f32.bf16.bf16.f32 "                   \
        "{%0,%1,%2,%3}, {%4,%5,%6,%7}, {%8,%9}, {%0,%1,%2,%3};"                  \
        : "+f"(C[0]), "+f"(C[1]), "+f"(C[2]), "+f"(C[3])                         \
        : "r"(A[0]), "r"(A[1]), "r"(A[2]), "r"(A[3]), "r"(B[0]), "r"(B[1]))

template <int FOUT>
__global__ __launch_bounds__(256) void k_gemm_mma(const float* __restrict__ Xext,
                                                  const float* __restrict__ W,
                                                  int in_sel, int K, int relu_in) {
    const float* X = (in_sel == 0) ? Xext : (const float*)g_buf1;
    constexpr int PAD = 40;
    __shared__ __align__(16) __nv_bfloat16 sAh[128 * PAD];
    __shared__ __align__(16) __nv_bfloat16 sAl[128 * PAD];
    __shared__ __align__(16) __nv_bfloat16 sBh[FOUT * PAD];
    __shared__ __align__(16) __nv_bfloat16 sBl[FOUT * PAD];
    const int t = threadIdx.x, lane = t & 31, warp = t >> 5;
    const int gid = lane >> 2, tig = lane & 3;
    const int row0 = blockIdx.x * 128;
    constexpr int NT = FOUT / 8;
    float acc[NT][4];
#pragma unroll
    for (int n = 0; n < NT; n++)
#pragma unroll
        for (int c = 0; c < 4; c++) acc[n][c] = 0.f;

    for (int k0 = 0; k0 < K; k0 += 32) {
        __syncthreads();
        // A tile 128x32: hi/lo split
        for (int i = t; i < 128 * 16; i += 256) {
            int r = i >> 4, kp = (i & 15) << 1;
            float2 v = make_float2(0.f, 0.f);
            int row = row0 + r;
            if (row < NN) v = *(const float2*)&X[row * K + k0 + kp];
            if (relu_in) { v.x = fmaxf(v.x, 0.f); v.y = fmaxf(v.y, 0.f); }
            __nv_bfloat16 h0 = __float2bfloat16(v.x), h1 = __float2bfloat16(v.y);
            __nv_bfloat16 l0 = __float2bfloat16(v.x - __bfloat162float(h0));
            __nv_bfloat16 l1 = __float2bfloat16(v.y - __bfloat162float(h1));
            *(__nv_bfloat162*)&sAh[r * PAD + kp] = __halves2bfloat162(h0, h1);
            *(__nv_bfloat162*)&sAl[r * PAD + kp] = __halves2bfloat162(l0, l1);
        }
        // B tile 32xFOUT, transposed into [n][k]
        for (int i = t; i < 32 * FOUT; i += 256) {
            int kk = i / FOUT, n = i - kk * FOUT;
            float w = W[(k0 + kk) * FOUT + n];
            __nv_bfloat16 h = __float2bfloat16(w);
            sBh[n * PAD + kk] = h;
            sBl[n * PAD + kk] = __float2bfloat16(w - __bfloat162float(h));
        }
        __syncthreads();
#pragma unroll
        for (int ks = 0; ks < 32; ks += 16) {
            const __nv_bfloat16* pa = &sAh[(warp * 16 + gid) * PAD + ks + tig * 2];
            const __nv_bfloat16* pl = &sAl[(warp * 16 + gid) * PAD + ks + tig * 2];
            uint32_t ah[4], al[4];
            ah[0] = *(const uint32_t*)pa;
            ah[1] = *(const uint32_t*)(pa + 8 * PAD);
            ah[2] = *(const uint32_t*)(pa + 8);
            ah[3] = *(const uint32_t*)(pa + 8 * PAD + 8);
            al[0] = *(const uint32_t*)pl;
            al[1] = *(const uint32_t*)(pl + 8 * PAD);
            al[2] = *(const uint32_t*)(pl + 8);
            al[3] = *(const uint32_t*)(pl + 8 * PAD + 8);
#pragma unroll
            for (int nt = 0; nt < NT; nt++) {
                const __nv_bfloat16* pb = &sBh[(nt * 8 + gid) * PAD + ks + tig * 2];
                const __nv_bfloat16* pq = &sBl[(nt * 8 + gid) * PAD + ks + tig * 2];
                uint32_t bh[2], bl[2];
                bh[0] = *(const uint32_t*)pb;
                bh[1] = *(const uint32_t*)(pb + 8);
                bl[0] = *(const uint32_t*)pq;
                bl[1] = *(const uint32_t*)(pq + 8);
                MMA_BF16(acc[nt], ah, bh);
                MMA_BF16(acc[nt], al, bh);
                MMA_BF16(acc[nt], ah, bl);
            }
        }
    }
    // epilogue: dinv scale + store
    int rA = row0 + warp * 16 + gid;
    int rB = rA + 8;
    float dA = (rA < NN) ? g_dinv[rA] : 0.f;
    float dB = (rB < NN) ? g_dinv[rB] : 0.f;
#pragma unroll
    for (int nt = 0; nt < NT; nt++) {
        int col = nt * 8 + tig * 2;
        if (rA < NN)
            *(float2*)&g_buf0[rA * FOUT + col] =
                make_float2(dA * acc[nt][0], dA * acc[nt][1]);
        if (rB < NN)
            *(float2*)&g_buf0[rB * FOUT + col] =
                make_float2(dB * acc[nt][2], dB * acc[nt][3]);
    }
}

// ---------------- aggregation ----------------
__global__ void k_agg96(const float* __restrict__ bias) {
    int wid = (blockIdx.x * blockDim.x + threadIdx.x) >> 5;
    int lane = threadIdx.x & 31;
    if (wid >= NN) return;
    int d = wid;
    int beg = g_off[d], end = g_off[d + 1];
    const float4* x4 = (const float4*)g_buf0;
    float4 acc = make_float4(0.f, 0.f, 0.f, 0.f);
    if (lane < 24) acc = x4[d * 24 + lane];   // self-loop
    for (int e = beg; e < end; e++) {
        int s = g_esrc[e];
        if (lane < 24) {
            float4 v = __ldg(&x4[s * 24 + lane]);
            acc.x += v.x; acc.y += v.y; acc.z += v.z; acc.w += v.w;
        }
    }
    if (lane < 24) {
        float sc = g_dinv[d];
        float4 b = ((const float4*)bias)[lane];
        float4 o;
        o.x = sc * acc.x + b.x; o.y = sc * acc.y + b.y;
        o.z = sc * acc.z + b.z; o.w = sc * acc.w + b.w;
        ((float4*)g_buf1)[d * 24 + lane] = o;
    }
}

__global__ void k_agg32(const float* __restrict__ bias, float* __restrict__ out) {
    int wid = (blockIdx.x * blockDim.x + threadIdx.x) >> 5;
    int lane = threadIdx.x & 31;
    if (wid >= NN) return;
    int d = wid;
    int grp = lane >> 3, fl = lane & 7;
    const float4* x4 = (const float4*)g_buf0;
    float4 acc = make_float4(0.f, 0.f, 0.f, 0.f);
    if (grp == 0) acc = x4[d * 8 + fl];       // self-loop
    int beg = g_off[d], end = g_off[d + 1];
    for (int e = beg + grp; e < end; e += 4) {
        int s = g_esrc[e];
        float4 v = __ldg(&x4[s * 8 + fl]);
        acc.x += v.x; acc.y += v.y; acc.z += v.z; acc.w += v.w;
    }
#pragma unroll
    for (int o = 8; o <= 16; o <<= 1) {
        acc.x += __shfl_xor_sync(0xFFFFFFFF, acc.x, o);
        acc.y += __shfl_xor_sync(0xFFFFFFFF, acc.y, o);
        acc.z += __shfl_xor_sync(0xFFFFFFFF, acc.z, o);
        acc.w += __shfl_xor_sync(0xFFFFFFFF, acc.w, o);
    }
    if (lane < 8) {
        float sc = g_dinv[d];
        float4 b = ((const float4*)bias)[fl];
        float4 o;
        o.x = sc * acc.x + b.x; o.y = sc * acc.y + b.y;
        o.z = sc * acc.z + b.z; o.w = sc * acc.w + b.w;
        ((float4*)out)[d * 8 + fl] = o;
    }
}

// ---------------- log_softmax over 32 classes ----------------
__global__ void k_lsm(float* __restrict__ out) {
    int wid = (blockIdx.x * blockDim.x + threadIdx.x) >> 5;
    int lane = threadIdx.x & 31;
    if (wid >= NN) return;
    float v = out[wid * 32 + lane];
    float m = v;
#pragma unroll
    for (int o = 16; o >= 1; o >>= 1) m = fmaxf(m, __shfl_xor_sync(0xFFFFFFFF, m, o));
    float e = expf(v - m);
    float s = e;
#pragma unroll
    for (int o = 16; o >= 1; o >>= 1) s += __shfl_xor_sync(0xFFFFFFFF, s, o);
    out[wid * 32 + lane] = v - m - logf(s);
}

// ---------------- launch ----------------
extern "C" void kernel_launch(void* const* d_in, const int* in_sizes, int n_in,
                              void* d_out, int out_size) {
    const float* x  = (const float*)d_in[0];
    const int*   ei = (const int*)d_in[1];     // JAX x64 disabled -> int32
    const float* W1 = (const float*)d_in[2];
    const float* b1 = (const float*)d_in[3];
    const float* W2 = (const float*)d_in[4];
    const float* b2 = (const float*)d_in[5];
    const float* W3 = (const float*)d_in[6];
    const float* b3 = (const float*)d_in[7];
    float* out = (float*)d_out;

    const int* src = ei;
    const int* dst = ei + EE;

    const int NB_SCAN = (NN + 511) / 512;

    k_zero_deg<<<(NN + 255) / 256, 256>>>();
    k_count<<<(EE + 255) / 256, 256>>>(dst);
    k_scan1<<<NB_SCAN, 512>>>();
    k_scan2<<<1, 128>>>(NB_SCAN);
    k_scan3<<<(NN + 255) / 256, 256>>>();
    k_fill<<<(EE + 255) / 256, 256>>>(src, dst);

    const int GT = (NN + 127) / 128;         // gemm tiles (128 rows each)
    const int AB = (NN * 32 + 255) / 256;    // warp-per-node blocks

    // layer 1: x[50000,128] @ W1[128,96]
    k_gemm_mma<96><<<GT, 256>>>(x, W1, 0, 128, 0);
    k_agg96<<<AB, 256>>>(b1);
    // layer 2: relu(h1) @ W2[96,96]
    k_gemm_mma<96><<<GT, 256>>>(x, W2, 1, 96, 1);
    k_agg96<<<AB, 256>>>(b2);
    // layer 3: relu(h2) @ W3[96,32]
    k_gemm_mma<32><<<GT, 256>>>(x, W3, 1, 96, 1);
    k_agg32<<<AB, 256>>>(b3, out);

    k_lsm<<<AB, 256>>>(out);
}

// round 8
// speedup vs baseline: 1.4695x; 1.0127x over previous
#include <cuda_runtime.h>
#include <cuda_bf16.h>
#include <cstdint>

#define NN 50000
#define EE 800000

__device__ float g_buf0[NN * 96];
__device__ float g_buf1[NN * 96];
__device__ int   g_deg[NN];
__device__ float g_dinv[NN];
__device__ int   g_off[NN + 1];
__device__ int   g_cur[NN];
__device__ int   g_esrc[EE];
__device__ int   g_bsum[64];

__global__ void k_zero_deg() {
    int i = blockIdx.x * blockDim.x + threadIdx.x;
    if (i < NN) g_deg[i] = 0;
}

__global__ void k_count(const int* __restrict__ dst) {
    int e = blockIdx.x * blockDim.x + threadIdx.x;
    if (e < EE) atomicAdd(&g_deg[dst[e]], 1);
}

__global__ void k_scan1() {
    __shared__ int sh[1024];
    int t = threadIdx.x;
    int i = blockIdx.x * 1024 + t;
    int v = (i < NN) ? g_deg[i] : 0;
    sh[t] = v;
    for (int o = 1; o < 1024; o <<= 1) {
        __syncthreads();
        int tmp = (t >= o) ? sh[t - o] : 0;
        __syncthreads();
        sh[t] += tmp;
    }
    __syncthreads();
    if (i < NN) g_off[i] = sh[t] - v;
    if (t == 1023) g_bsum[blockIdx.x] = sh[1023];
}

// finalize: inline exclusive prefix of <=64 block sums (done redundantly per
// block by thread 0's warp via lane-serial add — 64 ints, trivial), then offsets.
__global__ void k_scan3(int nb) {
    __shared__ int sb[64];
    int t = threadIdx.x;
    // warp 0, lane-parallel inclusive scan via shfl over two 32-chunks
    if (t < 64) {
        int v = (t < nb) ? g_bsum[t] : 0;
        sb[t] = v;
    }
    __syncthreads();
    if (t == 0) {
        int acc = 0;
#pragma unroll
        for (int j = 0; j < 64; j++) { int v = sb[j]; sb[j] = acc; acc += v; }
    }
    __syncthreads();
    int i = blockIdx.x * blockDim.x + threadIdx.x;
    if (i < NN) {
        int o = g_off[i] + sb[i >> 10];
        g_off[i] = o;
        g_cur[i] = o;
        g_dinv[i] = rsqrtf((float)(g_deg[i] + 1));
    }
    if (i == 0) g_off[NN] = EE;
}

__global__ void k_fill(const int* __restrict__ src, const int* __restrict__ dst) {
    int e = blockIdx.x * blockDim.x + threadIdx.x;
    if (e < EE) {
        int d = dst[e];
        int p = atomicAdd(&g_cur[d], 1);
        g_esrc[p] = src[e];
    }
}

#define MMA_BF16(C, A, B)                                                        \
    asm volatile(                                                                \
        "mma.sync.aligned.m16n8k16.row.col.f32.bf16.bf16.f32 "                   \
        "{%0,%1,%2,%3}, {%4,%5,%6,%7}, {%8,%9}, {%0,%1,%2,%3};"                  \
        : "+f"(C[0]), "+f"(C[1]), "+f"(C[2]), "+f"(C[3])                         \
        : "r"(A[0]), "r"(A[1]), "r"(A[2]), "r"(A[3]), "r"(B[0]), "r"(B[1]))

template <int FOUT>
__global__ __launch_bounds__(256) void k_gemm_mma(const float* __restrict__ Xext,
                                                  const float* __restrict__ W,
                                                  int in_sel, int K, int relu_in) {
    const float* X = (in_sel == 0) ? Xext : (const float*)g_buf1;
    constexpr int PAD = 40;
    __shared__ __align__(16) __nv_bfloat16 sAh[128 * PAD];
    __shared__ __align__(16) __nv_bfloat16 sAl[128 * PAD];
    __shared__ __align__(16) __nv_bfloat16 sBh[FOUT * PAD];
    __shared__ __align__(16) __nv_bfloat16 sBl[FOUT * PAD];
    const int t = threadIdx.x, lane = t & 31, warp = t >> 5;
    const int gid = lane >> 2, tig = lane & 3;
    const int row0 = blockIdx.x * 128;
    constexpr int NT = FOUT / 8;
    float acc[NT][4];
#pragma unroll
    for (int n = 0; n < NT; n++)
#pragma unroll
        for (int c = 0; c < 4; c++) acc[n][c] = 0.f;

    for (int k0 = 0; k0 < K; k0 += 32) {
        __syncthreads();
        for (int i = t; i < 128 * 16; i += 256) {
            int r = i >> 4, kp = (i & 15) << 1;
            float2 v = make_float2(0.f, 0.f);
            int row = row0 + r;
            if (row < NN) v = *(const float2*)&X[row * K + k0 + kp];
            if (relu_in) { v.x = fmaxf(v.x, 0.f); v.y = fmaxf(v.y, 0.f); }
            __nv_bfloat16 h0 = __float2bfloat16(v.x), h1 = __float2bfloat16(v.y);
            __nv_bfloat16 l0 = __float2bfloat16(v.x - __bfloat162float(h0));
            __nv_bfloat16 l1 = __float2bfloat16(v.y - __bfloat162float(h1));
            *(__nv_bfloat162*)&sAh[r * PAD + kp] = __halves2bfloat162(h0, h1);
            *(__nv_bfloat162*)&sAl[r * PAD + kp] = __halves2bfloat162(l0, l1);
        }
        for (int i = t; i < 32 * FOUT; i += 256) {
            int kk = i / FOUT, n = i - kk * FOUT;
            float w = W[(k0 + kk) * FOUT + n];
            __nv_bfloat16 h = __float2bfloat16(w);
            sBh[n * PAD + kk] = h;
            sBl[n * PAD + kk] = __float2bfloat16(w - __bfloat162float(h));
        }
        __syncthreads();
#pragma unroll
        for (int ks = 0; ks < 32; ks += 16) {
            const __nv_bfloat16* pa = &sAh[(warp * 16 + gid) * PAD + ks + tig * 2];
            const __nv_bfloat16* pl = &sAl[(warp * 16 + gid) * PAD + ks + tig * 2];
            uint32_t ah[4], al[4];
            ah[0] = *(const uint32_t*)pa;
            ah[1] = *(const uint32_t*)(pa + 8 * PAD);
            ah[2] = *(const uint32_t*)(pa + 8);
            ah[3] = *(const uint32_t*)(pa + 8 * PAD + 8);
            al[0] = *(const uint32_t*)pl;
            al[1] = *(const uint32_t*)(pl + 8 * PAD);
            al[2] = *(const uint32_t*)(pl + 8);
            al[3] = *(const uint32_t*)(pl + 8 * PAD + 8);
#pragma unroll
            for (int nt = 0; nt < NT; nt++) {
                const __nv_bfloat16* pb = &sBh[(nt * 8 + gid) * PAD + ks + tig * 2];
                const __nv_bfloat16* pq = &sBl[(nt * 8 + gid) * PAD + ks + tig * 2];
                uint32_t bh[2], bl[2];
                bh[0] = *(const uint32_t*)pb;
                bh[1] = *(const uint32_t*)(pb + 8);
                bl[0] = *(const uint32_t*)pq;
                bl[1] = *(const uint32_t*)(pq + 8);
                MMA_BF16(acc[nt], ah, bh);
                MMA_BF16(acc[nt], al, bh);
                MMA_BF16(acc[nt], ah, bl);
            }
        }
    }
    int rA = row0 + warp * 16 + gid;
    int rB = rA + 8;
    float dA = (rA < NN) ? g_dinv[rA] : 0.f;
    float dB = (rB < NN) ? g_dinv[rB] : 0.f;
#pragma unroll
    for (int nt = 0; nt < NT; nt++) {
        int col = nt * 8 + tig * 2;
        if (rA < NN)
            *(float2*)&g_buf0[rA * FOUT + col] =
                make_float2(dA * acc[nt][0], dA * acc[nt][1]);
        if (rB < NN)
            *(float2*)&g_buf0[rB * FOUT + col] =
                make_float2(dB * acc[nt][2], dB * acc[nt][3]);
    }
}

__global__ void k_agg96(const float* __restrict__ bias) {
    int wid = (blockIdx.x * blockDim.x + threadIdx.x) >> 5;
    int lane = threadIdx.x & 31;
    if (wid >= NN) return;
    int d = wid;
    int beg = g_off[d], end = g_off[d + 1];
    const float4* x4 = (const float4*)g_buf0;
    float4 acc = make_float4(0.f, 0.f, 0.f, 0.f);
    if (lane < 24) acc = x4[d * 24 + lane];
    for (int e = beg; e < end; e++) {
        int s = g_esrc[e];
        if (lane < 24) {
            float4 v = __ldg(&x4[s * 24 + lane]);
            acc.x += v.x; acc.y += v.y; acc.z += v.z; acc.w += v.w;
        }
    }
    if (lane < 24) {
        float sc = g_dinv[d];
        float4 b = ((const float4*)bias)[lane];
        float4 o;
        o.x = sc * acc.x + b.x; o.y = sc * acc.y + b.y;
        o.z = sc * acc.z + b.z; o.w = sc * acc.w + b.w;
        ((float4*)g_buf1)[d * 24 + lane] = o;
    }
}

__global__ void k_agg32lsm(const float* __restrict__ bias, float* __restrict__ out) {
    int wid = (blockIdx.x * blockDim.x + threadIdx.x) >> 5;
    int lane = threadIdx.x & 31;
    if (wid >= NN) return;
    int d = wid;
    int grp = lane >> 3, fl = lane & 7;
    const float4* x4 = (const float4*)g_buf0;
    float4 acc = make_float4(0.f, 0.f, 0.f, 0.f);
    if (grp == 0) acc = x4[d * 8 + fl];
    int beg = g_off[d], end = g_off[d + 1];
    for (int e = beg + grp; e < end; e += 4) {
        int s = g_esrc[e];
        float4 v = __ldg(&x4[s * 8 + fl]);
        acc.x += v.x; acc.y += v.y; acc.z += v.z; acc.w += v.w;
    }
#pragma unroll
    for (int o = 8; o <= 16; o <<= 1) {
        acc.x += __shfl_xor_sync(0xFFFFFFFF, acc.x, o);
        acc.y += __shfl_xor_sync(0xFFFFFFFF, acc.y, o);
        acc.z += __shfl_xor_sync(0xFFFFFFFF, acc.z, o);
        acc.w += __shfl_xor_sync(0xFFFFFFFF, acc.w, o);
    }
    float sc = g_dinv[d];
    float4 b = ((const float4*)bias)[fl];
    float4 v;
    v.x = sc * acc.x + b.x; v.y = sc * acc.y + b.y;
    v.z = sc * acc.z + b.z; v.w = sc * acc.w + b.w;
    float m = fmaxf(fmaxf(v.x, v.y), fmaxf(v.z, v.w));
#pragma unroll
    for (int o = 1; o <= 4; o <<= 1) m = fmaxf(m, __shfl_xor_sync(0xFFFFFFFF, m, o));
    float s = expf(v.x - m) + expf(v.y - m) + expf(v.z - m) + expf(v.w - m);
#pragma unroll
    for (int o = 1; o <= 4; o <<= 1) s += __shfl_xor_sync(0xFFFFFFFF, s, o);
    float ls = m + logf(s);
    if (grp == 0) {
        float4 o4 = make_float4(v.x - ls, v.y - ls, v.z - ls, v.w - ls);
        ((float4*)out)[d * 8 + fl] = o4;
    }
}

extern "C" void kernel_launch(void* const* d_in, const int* in_sizes, int n_in,
                              void* d_out, int out_size) {
    const float* x  = (const float*)d_in[0];
    const int*   ei = (const int*)d_in[1];
    const float* W1 = (const float*)d_in[2];
    const float* b1 = (const float*)d_in[3];
    const float* W2 = (const float*)d_in[4];
    const float* b2 = (const float*)d_in[5];
    const float* W3 = (const float*)d_in[6];
    const float* b3 = (const float*)d_in[7];
    float* out = (float*)d_out;

    const int* src = ei;
    const int* dst = ei + EE;

    const int NB_SCAN = (NN + 1023) / 1024;

    k_zero_deg<<<(NN + 255) / 256, 256>>>();
    k_count<<<(EE + 511) / 512, 512>>>(dst);
    k_scan1<<<NB_SCAN, 1024>>>();
    k_scan3<<<(NN + 255) / 256, 256>>>(NB_SCAN);
    k_fill<<<(EE + 511) / 512, 512>>>(src, dst);

    const int GT = (NN + 127) / 128;
    const int AB = (NN * 32 + 255) / 256;

    k_gemm_mma<96><<<GT, 256>>>(x, W1, 0, 128, 0);
    k_agg96<<<AB, 256>>>(b1);
    k_gemm_mma<96><<<GT, 256>>>(x, W2, 1, 96, 1);
    k_agg96<<<AB, 256>>>(b2);
    k_gemm_mma<32><<<GT, 256>>>(x, W3, 1, 96, 1);
    k_agg32lsm<<<AB, 256>>>(b3, out);
}